// round 16
// baseline (speedup 1.0000x reference)
#include <cuda_runtime.h>
#include <cuda_fp16.h>

// FINAL — converged best (measured 168.4-168.7 us across 3 runs; rel_err 2.1e-4).
//
// Two kernels:
//   1) dav_reduce_c: per-pixel channel reductions (num=sum_c q*k_d,
//      kk=sum_c k_d^2, qq=sum_c q^2) streaming 1.03 GB of compulsory input
//      at ~6.7 TB/s (84-85% DRAM = measured LTS cap) — the pipeline floor.
//      Results stored fp16-compressed (half2(num,kk)) into a zero-padded
//      scratch, halving the scratch round-trip vs fp32.
//   2) dav_box_norm: 3x3 zero-padded box filter + cosine normalize with
//      fused nq, rsqrt epilogue, shared transpose for coalesced stores.
//
// Shapes (fixed by the problem):
//   q:           [B=2, C=64, H=192, W=320]            fp32
//   warped_feat: [B=2, C=64, H=192, W=320, D=32]      fp32
//   out (sim):   [B=2, D=32, H=192, W=320]            fp32
#define B_  2
#define C_  64
#define H_  192
#define W_  320
#define D_  32
#define HW_ (H_ * W_)
#define NPIX (B_ * HW_)            // 122880
#define HP_ (H_ + 2)               // padded
#define WP_ (W_ + 2)
#define PPIX (B_ * HP_ * WP_)      // padded pixel count
#define EPS2_ 1e-24f               // eps^2 for rsqrt(max(x, eps^2))

#define NB_MAIN   (NPIX / 32)      // 3840 main blocks in reduce kernel
#define NBORDER   (B_ * 1028)      // ring cells to zero
#define NB_BORDER ((NBORDER + 255) / 256)   // 9 extra blocks

// Box tiling: 8w x 8h per block, 256 threads (warp = one output row, lane = d)
#define TW_ 8
#define TH_ 8
#define NB_X (B_ * (H_ / TH_) * (W_ / TW_))  // 1920 box blocks

// Scratch, fp16-compressed (~17 MB; effectively L2-resident between kernels).
// g_nkh[pp*D + d] = half2(num, kk). num ~ N(0,64), kk ~ 64±12 — well inside
// fp16 range (~3e-4 RMS rel quant error, ~5x under the 1e-3 threshold).
// Zero-padded 1-pixel border so the 3x3 box needs no bounds checks.
__device__ __half2 g_nkh[(size_t)PPIX * D_];   // ~16 MB
__device__ float   g_qqp[PPIX];                // padded sum_c q^2 (fp32)

// ---------------------------------------------------------------------------
// Kernel 1: per-pixel reduction over C. 8 threads/pixel, float4 over d;
// each warp's k loads cover contiguous 512B spans (fully coalesced LDG.128).
// unroll 4 + 5 blocks/SM (62.5% occ) is the measured sweet spot.
// Trailing blocks zero the border ring (fused to save a launch).
// ---------------------------------------------------------------------------
__global__ __launch_bounds__(256, 5)
void dav_reduce_c(const float* __restrict__ q, const float* __restrict__ k)
{
    if (blockIdx.x >= NB_MAIN) {
        const int t = (blockIdx.x - NB_MAIN) * 256 + threadIdx.x;
        if (t >= NBORDER) return;
        const int b = t / 1028;
        const int i = t - b * 1028;
        int hp, wp;
        if (i < WP_)          { hp = 0;       wp = i; }
        else if (i < 2 * WP_) { hp = H_ + 1;  wp = i - WP_; }
        else { const int j = i - 2 * WP_;     // j in [0, 2*H)
               hp = 1 + (j >> 1);  wp = (j & 1) ? (W_ + 1) : 0; }

        const size_t pp = ((size_t)b * HP_ + hp) * WP_ + wp;
        uint4* o = reinterpret_cast<uint4*>(g_nkh + pp * D_);
        #pragma unroll
        for (int m = 0; m < 8; ++m) o[m] = make_uint4(0u, 0u, 0u, 0u);
        g_qqp[pp] = 0.f;
        return;
    }

    const int tid = threadIdx.x;
    const int grp = tid >> 3;          // pixel within block: 0..31
    const int sub = tid & 7;           // d-quad: 0..7
    const int pix = blockIdx.x * 32 + grp;

    const int b  = pix / HW_;
    const int hw = pix - b * HW_;
    const int h  = hw / W_;
    const int w  = hw - h * W_;

    const float* __restrict__ qp = q + (size_t)b * C_ * HW_ + hw;
    const float* __restrict__ kp = k + ((size_t)b * C_ * HW_ + hw) * D_ + sub * 4;

    float4 num = make_float4(0.f, 0.f, 0.f, 0.f);
    float4 kk  = make_float4(0.f, 0.f, 0.f, 0.f);
    float  qq  = 0.f;

    const size_t kstride = (size_t)HW_ * D_;

    #pragma unroll 4
    for (int c = 0; c < C_; ++c) {
        const float  qv = __ldg(qp + (size_t)c * HW_);
        const float4 kv = *reinterpret_cast<const float4*>(kp + (size_t)c * kstride);
        num.x = fmaf(qv, kv.x, num.x);
        num.y = fmaf(qv, kv.y, num.y);
        num.z = fmaf(qv, kv.z, num.z);
        num.w = fmaf(qv, kv.w, num.w);
        kk.x  = fmaf(kv.x, kv.x, kk.x);
        kk.y  = fmaf(kv.y, kv.y, kk.y);
        kk.z  = fmaf(kv.z, kv.z, kk.z);
        kk.w  = fmaf(kv.w, kv.w, kk.w);
        qq    = fmaf(qv, qv, qq);
    }

    const size_t pp = ((size_t)b * HP_ + h + 1) * WP_ + (w + 1);
    __half2 hv[4];
    hv[0] = __floats2half2_rn(num.x, kk.x);
    hv[1] = __floats2half2_rn(num.y, kk.y);
    hv[2] = __floats2half2_rn(num.z, kk.z);
    hv[3] = __floats2half2_rn(num.w, kk.w);
    *reinterpret_cast<uint4*>(g_nkh + pp * D_ + sub * 4) =
        *reinterpret_cast<const uint4*>(hv);
    if (sub == 0) g_qqp[pp] = qq;
}

// ---------------------------------------------------------------------------
// Kernel 2: 3x3 box + normalize (half2 scratch).
// Block = 256 thr = 8 warps; warp = one output row (8 wide), lane = d.
// Phase A: 10 column sums staged in one pass (30 independent loads/warp
//          covering the memory latency in one round trip); qq (nq) fused
//          as lane-invariant broadcast loads.
// Phase B: register sliding sums + rsqrt (fp32 accumulation).
// Phase C: shared transpose -> coalesced [b,d,h,w] stores (32B runs).
// ---------------------------------------------------------------------------
__global__ __launch_bounds__(256, 5)
void dav_box_norm(float* __restrict__ out)
{
    __shared__ float s[TH_][TW_][33];

    const int tid  = threadIdx.x;
    const int lane = tid & 31;          // = d
    const int wid  = tid >> 5;          // output row within tile: 0..7

    int t = blockIdx.x;
    const int wt = t % (W_ / TW_);  t /= (W_ / TW_);
    const int ht = t % (H_ / TH_);  const int b = t / (H_ / TH_);

    const int hb = ht * TH_;
    const int h  = hb + wid;
    const int w0 = wt * TW_;

    const int pitch = WP_ * D_;
    const __half2* __restrict__ base =
        g_nkh + (((size_t)b * HP_ + h + 1) * WP_ + w0) * D_ + lane;
    const float* __restrict__ qb =
        g_qqp + ((size_t)b * HP_ + h + 1) * WP_ + w0;

    // Phase A: column sums for the 10 padded columns covering outputs w0..w0+7.
    float2 cs[10];
    float  qs[10];
    #pragma unroll
    for (int j = 0; j < 10; ++j) {
        const int o = j * D_;
        const float2 a = __half22float2(base[o - pitch]);
        const float2 c = __half22float2(base[o]);
        const float2 e = __half22float2(base[o + pitch]);
        cs[j] = make_float2(a.x + c.x + e.x, a.y + c.y + e.y);
        qs[j] = qb[j - WP_] + qb[j] + qb[j + WP_];
    }

    // Phase B: sliding 3-column sums + normalize, straight into smem.
    #pragma unroll
    for (int i = 0; i < TW_; ++i) {
        const float num = cs[i].x + cs[i + 1].x + cs[i + 2].x;
        const float kk  = cs[i].y + cs[i + 1].y + cs[i + 2].y;
        const float qq  = qs[i]   + qs[i + 1]   + qs[i + 2];
        s[wid][i][lane] = num * rsqrtf(fmaxf(qq, EPS2_))
                              * rsqrtf(fmaxf(kk, EPS2_));
    }
    __syncthreads();

    // Phase C: 2048 outputs (8h x 8w x 32d), 8 stores/thread; each warp
    // store = 4 runs of 8 consecutive floats (32B sectors).
    const int ow = tid & 7;             // w within tile
    const int rr = tid >> 3;            // 0..31
    const size_t obase = (size_t)b * D_ * HW_ + w0 + ow;
    #pragma unroll
    for (int i = 0; i < 8; ++i) {
        const int idx = i * 32 + rr;    // 0..255 -> (d, hl)
        const int d   = idx >> 3;
        const int hl  = idx & 7;
        out[obase + ((size_t)d * H_ + hb + hl) * W_] = s[hl][ow][d];
    }
}

// ---------------------------------------------------------------------------
extern "C" void kernel_launch(void* const* d_in, const int* in_sizes, int n_in,
                              void* d_out, int out_size)
{
    const float* q = (const float*)d_in[0];     // [B,C,H,W]
    const float* k = (const float*)d_in[1];     // [B,C,H,W,D]
    float* out     = (float*)d_out;             // [B,D,H,W]

    dav_reduce_c<<<NB_MAIN + NB_BORDER, 256>>>(q, k);
    dav_box_norm<<<NB_X, 256>>>(out);
}

// round 17
// speedup vs baseline: 1.0042x; 1.0042x over previous
#include <cuda_runtime.h>
#include <cuda_fp16.h>

// FINAL — converged best (168.6 ± 0.3 us across 4 runs; rel_err 2.1e-4).
//
// Two kernels:
//   1) dav_reduce_c: per-pixel channel reductions (num=sum_c q*k_d,
//      kk=sum_c k_d^2, qq=sum_c q^2) streaming 1.03 GB of compulsory input
//      at ~6.7 TB/s (84-85% DRAM = measured LTS cap) — the pipeline floor.
//      Results stored fp16-compressed (half2(num,kk)) into a zero-padded
//      scratch, halving the scratch round-trip vs fp32.
//   2) dav_box_norm: 3x3 zero-padded box filter + cosine normalize with
//      fused nq, rsqrt epilogue, shared transpose for coalesced stores.
//
// Shapes (fixed by the problem):
//   q:           [B=2, C=64, H=192, W=320]            fp32
//   warped_feat: [B=2, C=64, H=192, W=320, D=32]      fp32
//   out (sim):   [B=2, D=32, H=192, W=320]            fp32
#define B_  2
#define C_  64
#define H_  192
#define W_  320
#define D_  32
#define HW_ (H_ * W_)
#define NPIX (B_ * HW_)            // 122880
#define HP_ (H_ + 2)               // padded
#define WP_ (W_ + 2)
#define PPIX (B_ * HP_ * WP_)      // padded pixel count
#define EPS2_ 1e-24f               // eps^2 for rsqrt(max(x, eps^2))

#define NB_MAIN   (NPIX / 32)      // 3840 main blocks in reduce kernel
#define NBORDER   (B_ * 1028)      // ring cells to zero
#define NB_BORDER ((NBORDER + 255) / 256)   // 9 extra blocks

// Box tiling: 8w x 8h per block, 256 threads (warp = one output row, lane = d)
#define TW_ 8
#define TH_ 8
#define NB_X (B_ * (H_ / TH_) * (W_ / TW_))  // 1920 box blocks

// Scratch, fp16-compressed (~17 MB; effectively L2-resident between kernels).
// g_nkh[pp*D + d] = half2(num, kk). num ~ N(0,64), kk ~ 64±12 — well inside
// fp16 range (~3e-4 RMS rel quant error, ~5x under the 1e-3 threshold).
// Zero-padded 1-pixel border so the 3x3 box needs no bounds checks.
__device__ __half2 g_nkh[(size_t)PPIX * D_];   // ~16 MB
__device__ float   g_qqp[PPIX];                // padded sum_c q^2 (fp32)

// ---------------------------------------------------------------------------
// Kernel 1: per-pixel reduction over C. 8 threads/pixel, float4 over d;
// each warp's k loads cover contiguous 512B spans (fully coalesced LDG.128).
// unroll 4 + 5 blocks/SM (62.5% occ) is the measured sweet spot.
// Trailing blocks zero the border ring (fused to save a launch).
// ---------------------------------------------------------------------------
__global__ __launch_bounds__(256, 5)
void dav_reduce_c(const float* __restrict__ q, const float* __restrict__ k)
{
    if (blockIdx.x >= NB_MAIN) {
        const int t = (blockIdx.x - NB_MAIN) * 256 + threadIdx.x;
        if (t >= NBORDER) return;
        const int b = t / 1028;
        const int i = t - b * 1028;
        int hp, wp;
        if (i < WP_)          { hp = 0;       wp = i; }
        else if (i < 2 * WP_) { hp = H_ + 1;  wp = i - WP_; }
        else { const int j = i - 2 * WP_;     // j in [0, 2*H)
               hp = 1 + (j >> 1);  wp = (j & 1) ? (W_ + 1) : 0; }

        const size_t pp = ((size_t)b * HP_ + hp) * WP_ + wp;
        uint4* o = reinterpret_cast<uint4*>(g_nkh + pp * D_);
        #pragma unroll
        for (int m = 0; m < 8; ++m) o[m] = make_uint4(0u, 0u, 0u, 0u);
        g_qqp[pp] = 0.f;
        return;
    }

    const int tid = threadIdx.x;
    const int grp = tid >> 3;          // pixel within block: 0..31
    const int sub = tid & 7;           // d-quad: 0..7
    const int pix = blockIdx.x * 32 + grp;

    const int b  = pix / HW_;
    const int hw = pix - b * HW_;
    const int h  = hw / W_;
    const int w  = hw - h * W_;

    const float* __restrict__ qp = q + (size_t)b * C_ * HW_ + hw;
    const float* __restrict__ kp = k + ((size_t)b * C_ * HW_ + hw) * D_ + sub * 4;

    float4 num = make_float4(0.f, 0.f, 0.f, 0.f);
    float4 kk  = make_float4(0.f, 0.f, 0.f, 0.f);
    float  qq  = 0.f;

    const size_t kstride = (size_t)HW_ * D_;

    #pragma unroll 4
    for (int c = 0; c < C_; ++c) {
        const float  qv = __ldg(qp + (size_t)c * HW_);
        const float4 kv = *reinterpret_cast<const float4*>(kp + (size_t)c * kstride);
        num.x = fmaf(qv, kv.x, num.x);
        num.y = fmaf(qv, kv.y, num.y);
        num.z = fmaf(qv, kv.z, num.z);
        num.w = fmaf(qv, kv.w, num.w);
        kk.x  = fmaf(kv.x, kv.x, kk.x);
        kk.y  = fmaf(kv.y, kv.y, kk.y);
        kk.z  = fmaf(kv.z, kv.z, kk.z);
        kk.w  = fmaf(kv.w, kv.w, kk.w);
        qq    = fmaf(qv, qv, qq);
    }

    const size_t pp = ((size_t)b * HP_ + h + 1) * WP_ + (w + 1);
    __half2 hv[4];
    hv[0] = __floats2half2_rn(num.x, kk.x);
    hv[1] = __floats2half2_rn(num.y, kk.y);
    hv[2] = __floats2half2_rn(num.z, kk.z);
    hv[3] = __floats2half2_rn(num.w, kk.w);
    *reinterpret_cast<uint4*>(g_nkh + pp * D_ + sub * 4) =
        *reinterpret_cast<const uint4*>(hv);
    if (sub == 0) g_qqp[pp] = qq;
}

// ---------------------------------------------------------------------------
// Kernel 2: 3x3 box + normalize (half2 scratch).
// Block = 256 thr = 8 warps; warp = one output row (8 wide), lane = d.
// Phase A: 10 column sums staged in one pass (30 independent loads/warp
//          covering the memory latency in one round trip); qq (nq) fused
//          as lane-invariant broadcast loads.
// Phase B: register sliding sums + rsqrt (fp32 accumulation).
// Phase C: shared transpose -> coalesced [b,d,h,w] stores (32B runs).
// ---------------------------------------------------------------------------
__global__ __launch_bounds__(256, 5)
void dav_box_norm(float* __restrict__ out)
{
    __shared__ float s[TH_][TW_][33];

    const int tid  = threadIdx.x;
    const int lane = tid & 31;          // = d
    const int wid  = tid >> 5;          // output row within tile: 0..7

    int t = blockIdx.x;
    const int wt = t % (W_ / TW_);  t /= (W_ / TW_);
    const int ht = t % (H_ / TH_);  const int b = t / (H_ / TH_);

    const int hb = ht * TH_;
    const int h  = hb + wid;
    const int w0 = wt * TW_;

    const int pitch = WP_ * D_;
    const __half2* __restrict__ base =
        g_nkh + (((size_t)b * HP_ + h + 1) * WP_ + w0) * D_ + lane;
    const float* __restrict__ qb =
        g_qqp + ((size_t)b * HP_ + h + 1) * WP_ + w0;

    // Phase A: column sums for the 10 padded columns covering outputs w0..w0+7.
    float2 cs[10];
    float  qs[10];
    #pragma unroll
    for (int j = 0; j < 10; ++j) {
        const int o = j * D_;
        const float2 a = __half22float2(base[o - pitch]);
        const float2 c = __half22float2(base[o]);
        const float2 e = __half22float2(base[o + pitch]);
        cs[j] = make_float2(a.x + c.x + e.x, a.y + c.y + e.y);
        qs[j] = qb[j - WP_] + qb[j] + qb[j + WP_];
    }

    // Phase B: sliding 3-column sums + normalize, straight into smem.
    #pragma unroll
    for (int i = 0; i < TW_; ++i) {
        const float num = cs[i].x + cs[i + 1].x + cs[i + 2].x;
        const float kk  = cs[i].y + cs[i + 1].y + cs[i + 2].y;
        const float qq  = qs[i]   + qs[i + 1]   + qs[i + 2];
        s[wid][i][lane] = num * rsqrtf(fmaxf(qq, EPS2_))
                              * rsqrtf(fmaxf(kk, EPS2_));
    }
    __syncthreads();

    // Phase C: 2048 outputs (8h x 8w x 32d), 8 stores/thread; each warp
    // store = 4 runs of 8 consecutive floats (32B sectors).
    const int ow = tid & 7;             // w within tile
    const int rr = tid >> 3;            // 0..31
    const size_t obase = (size_t)b * D_ * HW_ + w0 + ow;
    #pragma unroll
    for (int i = 0; i < 8; ++i) {
        const int idx = i * 32 + rr;    // 0..255 -> (d, hl)
        const int d   = idx >> 3;
        const int hl  = idx & 7;
        out[obase + ((size_t)d * H_ + hb + hl) * W_] = s[hl][ow][d];
    }
}

// ---------------------------------------------------------------------------
extern "C" void kernel_launch(void* const* d_in, const int* in_sizes, int n_in,
                              void* d_out, int out_size)
{
    const float* q = (const float*)d_in[0];     // [B,C,H,W]
    const float* k = (const float*)d_in[1];     // [B,C,H,W,D]
    float* out     = (float*)d_out;             // [B,D,H,W]

    dav_reduce_c<<<NB_MAIN + NB_BORDER, 256>>>(q, k);
    dav_box_norm<<<NB_X, 256>>>(out);
}